// round 8
// baseline (speedup 1.0000x reference)
#include <cuda_runtime.h>
#include <cuda_bf16.h>

#define NB 4
#define NC 15
#define HH 320
#define FEATS 32
#define KS 11
#define KRBF 31
#define PH 342      // reflect-padded size (320 + 2*11)
#define UPD 352     // reflect + zero conv pad (342 + 2*5)
#define FUP 344     // pitch for f_u_k rows

// ---------------- static device scratch (no allocations allowed) ----------
__device__ float2 g_up[NB*UPD*UPD];          // (ur,ui) padded input
__device__ float  g_fu[NB*FEATS*PH*FUP];     // RBF(conv(u))
__device__ float2 g_ru[NB*HH*HH];            // regularizer output (cropped, /32)
__device__ float2 g_ks[NB*NC*HH*HH];         // k-space scratch

// ---------------- complex helpers ----------------
__device__ __forceinline__ float2 cmul(float2 a, float2 b){
    return make_float2(fmaf(a.x, b.x, -a.y*b.y), fmaf(a.x, b.y, a.y*b.x));
}
__device__ __forceinline__ float2 cadd(float2 a, float2 b){
    return make_float2(a.x+b.x, a.y+b.y);
}
__device__ __forceinline__ float2 cexp_(float ang){
    float s, c; __sincosf(ang, &s, &c); return make_float2(c, s);
}

#define TWO_PI 6.28318530717958647692f

// ---------------- 320-point Stockham FFT (radix 5*4*4*4) ------------------
// 80 threads per line (lt in [0,80)), ping-pong A/B, result in A natural order.
// ds = -1 forward, +1 inverse (unnormalized).
__device__ __forceinline__ void r4stage(const float2* __restrict__ src,
                                        float2* __restrict__ dst,
                                        int lt, int S, int M, int NN, float ds){
    int q = lt % S;
    int p = lt / S;            // p < M
    float2 a0 = src[q + S*p];
    float2 a1 = src[q + S*(p +   M)];
    float2 a2 = src[q + S*(p + 2*M)];
    float2 a3 = src[q + S*(p + 3*M)];
    float2 t0 = make_float2(a0.x+a2.x, a0.y+a2.y);
    float2 t1 = make_float2(a0.x-a2.x, a0.y-a2.y);
    float2 t2 = make_float2(a1.x+a3.x, a1.y+a3.y);
    float2 t3 = make_float2(a1.x-a3.x, a1.y-a3.y);
    float2 it3 = make_float2(-ds*t3.y, ds*t3.x);   // ds*i*t3
    float2 c0 = make_float2(t0.x+t2.x, t0.y+t2.y);
    float2 c2 = make_float2(t0.x-t2.x, t0.y-t2.y);
    float2 c1 = make_float2(t1.x+it3.x, t1.y+it3.y);
    float2 c3 = make_float2(t1.x-it3.x, t1.y-it3.y);
    float base = ds * TWO_PI * (float)p / (float)NN;
    dst[q + S*(4*p + 0)] = c0;
    dst[q + S*(4*p + 1)] = cmul(c1, cexp_(base));
    dst[q + S*(4*p + 2)] = cmul(c2, cexp_(base*2.f));
    dst[q + S*(4*p + 3)] = cmul(c3, cexp_(base*3.f));
}

__device__ void fft320(float2* __restrict__ A, float2* __restrict__ B,
                       int lt, float ds){
    // stage 1: n=320, r=5, s=1, m=64  (A -> B)
    if (lt < 64){
        int p = lt;
        float2 a0 = A[p], a1 = A[p+64], a2 = A[p+128], a3 = A[p+192], a4 = A[p+256];
        // k = 0 (no twiddles)
        B[5*p] = cadd(cadd(cadd(a0,a1), cadd(a2,a3)), a4);
        #pragma unroll
        for (int k = 1; k < 5; k++){
            float2 w1 = cexp_(ds * TWO_PI * 0.2f * (float)k);
            float2 wj = w1;
            float2 c = a0;
            c = cadd(c, cmul(a1, wj)); wj = cmul(wj, w1);
            c = cadd(c, cmul(a2, wj)); wj = cmul(wj, w1);
            c = cadd(c, cmul(a3, wj)); wj = cmul(wj, w1);
            c = cadd(c, cmul(a4, wj));
            float2 tw = cexp_(ds * TWO_PI * (float)(p*k) / 320.0f);
            B[5*p + k] = cmul(c, tw);
        }
    }
    __syncthreads();
    r4stage(B, A, lt,  5, 16, 64, ds);   // n=64
    __syncthreads();
    r4stage(A, B, lt, 20,  4, 16, ds);   // n=16
    __syncthreads();
    r4stage(B, A, lt, 80,  1,  4, ds);   // n=4 (twiddle = 1)
    __syncthreads();
}

// ---------------- K1: reflect + zero padding -------------------------------
__global__ void kpad(const float* __restrict__ u){
    int idx = blockIdx.x * blockDim.x + threadIdx.x;
    if (idx >= NB*UPD*UPD) return;
    int n  = idx / (UPD*UPD);
    int r  = idx % (UPD*UPD);
    int py = r / UPD, px = r % UPD;
    float2 v = make_float2(0.f, 0.f);
    if (!(py < 5 || py >= 347 || px < 5 || px >= 347)){
        int iy = py - 16, ix = px - 16;
        if (iy < 0) iy = -iy; else if (iy >= HH) iy = 2*HH - 2 - iy;
        if (ix < 0) ix = -ix; else if (ix >= HH) ix = 2*HH - 2 - ix;
        v = ((const float2*)u)[(n*HH + iy)*HH + ix];
    }
    g_up[idx] = v;
}

// ---------------- K2: forward conv (2->32 ch) + RBF, fused -----------------
// grid (11, 11, NB*FEATS), block (32, 8). 32x32 output tile, 4 outputs/thread in y.
__global__ __launch_bounds__(256) void kconv_rbf(const float* __restrict__ ck,
                                                 const float* __restrict__ w_,
                                                 const float* __restrict__ mu_,
                                                 const float* __restrict__ sigma_){
    __shared__ float2 sin_[42][42];
    __shared__ float2 swt[KS][KS];
    __shared__ float  sw[KRBF], smu[KRBF];

    int nz = blockIdx.z;
    int n  = nz / FEATS, oc = nz % FEATS;
    int x0 = blockIdx.x * 32, y0 = blockIdx.y * 32;
    int tx = threadIdx.x, ty = threadIdx.y;
    int tid = ty*32 + tx;

    if (tid < 121){
        const float* ckp = ck + oc*242 + tid*2;
        swt[tid/11][tid%11] = make_float2(ckp[0], ckp[1]);
    }
    if (tid < KRBF){ sw[tid] = w_[oc*KRBF + tid]; smu[tid] = mu_[tid]; }

    const float2* up = g_up + n*UPD*UPD;
    for (int i = tid; i < 42*42; i += 256){
        int r = i / 42, c = i % 42;
        int gy = y0 + r, gx = x0 + c;
        sin_[r][c] = (gy < UPD && gx < UPD) ? up[gy*UPD + gx] : make_float2(0.f,0.f);
    }
    __syncthreads();

    float acc[4] = {0.f, 0.f, 0.f, 0.f};
    int ry = ty * 4;
    #pragma unroll
    for (int kx = 0; kx < 11; kx++){
        float2 col[14];
        #pragma unroll
        for (int r = 0; r < 14; r++) col[r] = sin_[ry + r][tx + kx];
        #pragma unroll
        for (int ky = 0; ky < 11; ky++){
            float2 wv = swt[ky][kx];
            #pragma unroll
            for (int u = 0; u < 4; u++)
                acc[u] = fmaf(wv.x, col[ky+u].x, fmaf(wv.y, col[ky+u].y, acc[u]));
        }
    }

    float sg   = sigma_[0];
    float h    = 0.5f / (sg * sg);
    float mu0  = smu[0];
    float idel = 1.f / (smu[1] - smu[0]);

    #pragma unroll
    for (int u = 0; u < 4; u++){
        int gy = y0 + ry + u, gx = x0 + tx;
        if (gy < PH && gx < PH){
            float uv = acc[u];
            int j = __float2int_rn((uv - mu0) * idel);
            j = max(0, min(KRBF-1, j));
            float s_ = 0.f;
            #pragma unroll
            for (int d = -6; d <= 6; d++){
                int k = j + d;
                if (k >= 0 && k < KRBF){
                    float dd = uv - smu[k];
                    s_ += sw[k] * __expf(-h * dd * dd);
                }
            }
            g_fu[((n*FEATS + oc)*PH + gy)*FUP + gx] = s_;
        }
    }
}

// ---------------- K3: transposed conv (32->2 ch) + crop + /32 --------------
// grid (10, 10, NB), block (32,8). Output 320x320, no bounds checks needed.
__global__ __launch_bounds__(256) void kconvT(const float* __restrict__ ck){
    __shared__ float  sfu[42][44];
    __shared__ float2 swt[KS][KS];

    int n  = blockIdx.z;
    int x0 = blockIdx.x * 32, y0 = blockIdx.y * 32;
    int tx = threadIdx.x, ty = threadIdx.y;
    int tid = ty*32 + tx;
    int ry = ty * 4;

    float ar[4] = {0,0,0,0}, ai[4] = {0,0,0,0};

    for (int oc = 0; oc < FEATS; oc++){
        __syncthreads();
        if (tid < 121){
            int a = tid / 11, b = tid % 11;
            const float* ckp = ck + oc*242 + ((10-a)*11 + (10-b))*2;  // flipped
            swt[a][b] = make_float2(ckp[0], ckp[1]);
        }
        const float* fup = g_fu + (n*FEATS + oc)*PH*FUP;
        for (int i = tid; i < 42*42; i += 256){
            int r = i / 42, c = i % 42;
            sfu[r][c] = fup[(y0 + 6 + r)*FUP + (x0 + 6 + c)];
        }
        __syncthreads();

        #pragma unroll
        for (int kx = 0; kx < 11; kx++){
            float col[14];
            #pragma unroll
            for (int r = 0; r < 14; r++) col[r] = sfu[ry + r][tx + kx];
            #pragma unroll
            for (int ky = 0; ky < 11; ky++){
                float2 wv = swt[ky][kx];
                #pragma unroll
                for (int u = 0; u < 4; u++){
                    ar[u] = fmaf(wv.x, col[ky+u], ar[u]);
                    ai[u] = fmaf(wv.y, col[ky+u], ai[u]);
                }
            }
        }
    }

    const float inv = 1.f / (float)FEATS;
    #pragma unroll
    for (int u = 0; u < 4; u++){
        int gy = y0 + ry + u, gx = x0 + tx;
        g_ru[(n*HH + gy)*HH + gx] = make_float2(ar[u]*inv, ai[u]*inv);
    }
}

// ---------------- D1: row forward FFT of s*(u*coil) ------------------------
// grid NB*NC*80, block 320 (4 rows/block, 80 threads/row)
__global__ __launch_bounds__(320) void kfft_row_fwd(const float* __restrict__ u,
                                                    const float* __restrict__ coil){
    __shared__ float2 SA[4][320], SB[4][320];
    int b    = blockIdx.x;
    int ygrp = b % 80;
    int nc   = b / 80;
    int c    = nc % NC, n = nc / NC;
    int t    = threadIdx.x;
    int line = t / 80, lt = t % 80;
    int y    = ygrp*4 + line;

    const float2* up = (const float2*)u    + (n*HH + y)*HH;
    const float2* cp = (const float2*)coil + ((n*NC + c)*HH + y)*HH;
    #pragma unroll
    for (int j = 0; j < 4; j++){
        int x = lt + 80*j;
        float2 v = cmul(up[x], cp[x]);
        float sg = ((x + y) & 1) ? -1.f : 1.f;
        SA[line][x] = make_float2(v.x*sg, v.y*sg);
    }
    __syncthreads();
    fft320(SA[line], SB[line], lt, -1.f);

    float2* dst = g_ks + ((n*NC + c)*HH + y)*HH;
    #pragma unroll
    for (int j = 0; j < 4; j++){ int x = lt + 80*j; dst[x] = SA[line][x]; }
}

// ---------------- D2: column fwd FFT + mask/subtract + column inv FFT ------
__global__ __launch_bounds__(320) void kfft_col(const float* __restrict__ f,
                                                const float* __restrict__ mask){
    __shared__ float2 SA[4][320], SB[4][320];
    int b    = blockIdx.x;
    int xgrp = b % 80;
    int nc   = b / 80;
    int c    = nc % NC, n = nc / NC;
    int t    = threadIdx.x;
    int line = t / 80, lt = t % 80;
    int x    = xgrp*4 + line;

    float2* col = g_ks + (n*NC + c)*HH*HH + x;
    #pragma unroll
    for (int j = 0; j < 4; j++){ int y = lt + 80*j; SA[line][y] = col[y*HH]; }
    __syncthreads();
    fft320(SA[line], SB[line], lt, -1.f);

    const float sc = 1.f / 320.f;   // ortho fwd; another 1/320 folded for inverse
    #pragma unroll
    for (int j = 0; j < 4; j++){
        int ky = lt + 80*j;
        float2 V = SA[line][ky];
        float  m = mask[(n*HH + ky)*HH + x];
        float2 fv = ((const float2*)f)[((n*NC + c)*HH + ky)*HH + x];
        float sg = ((ky + x) & 1) ? -1.f : 1.f;
        float wx = m * (V.x*sc - sg*fv.x);
        float wy = m * (V.y*sc - sg*fv.y);
        SA[line][ky] = make_float2(wx*sc, wy*sc);
    }
    __syncthreads();
    fft320(SA[line], SB[line], lt, 1.f);
    #pragma unroll
    for (int j = 0; j < 4; j++){ int y = lt + 80*j; col[y*HH] = SA[line][y]; }
}

// ---------------- D3: row inverse FFT + coil-combine + final output --------
// grid NB*80, block 320. Loops over all 15 coils; writes out = u - Ru - Du.
__global__ __launch_bounds__(320) void kfft_row_inv(const float* __restrict__ u,
                                                    const float* __restrict__ coil,
                                                    const float* __restrict__ lamb,
                                                    float* __restrict__ outp){
    __shared__ float2 SA[4][320], SB[4][320];
    int b    = blockIdx.x;
    int ygrp = b % 80;
    int n    = b / 80;
    int t    = threadIdx.x;
    int line = t / 80, lt = t % 80;
    int y    = ygrp*4 + line;

    float2 du[4];
    #pragma unroll
    for (int j = 0; j < 4; j++) du[j] = make_float2(0.f, 0.f);

    for (int c = 0; c < NC; c++){
        const float2* src = g_ks + ((n*NC + c)*HH + y)*HH;
        __syncthreads();
        #pragma unroll
        for (int j = 0; j < 4; j++){ int x = lt + 80*j; SA[line][x] = src[x]; }
        __syncthreads();
        fft320(SA[line], SB[line], lt, 1.f);

        const float2* cp = (const float2*)coil + ((n*NC + c)*HH + y)*HH;
        #pragma unroll
        for (int j = 0; j < 4; j++){
            int x = lt + 80*j;
            float2 w2 = SA[line][x];
            float2 cc = cp[x];
            float sg = ((x + y) & 1) ? -1.f : 1.f;
            du[j].x += sg * ( w2.x*cc.x + w2.y*cc.y);
            du[j].y += sg * ( w2.y*cc.x - w2.x*cc.y);
        }
    }

    float lam = lamb[0];
    const float2* up  = (const float2*)u + (n*HH + y)*HH;
    const float2* rup = g_ru + (n*HH + y)*HH;
    float2* op = (float2*)outp + (n*HH + y)*HH;
    #pragma unroll
    for (int j = 0; j < 4; j++){
        int x = lt + 80*j;
        float2 uv = up[x];
        float2 rv = rup[x];
        op[x] = make_float2(uv.x - rv.x - lam*du[j].x,
                            uv.y - rv.y - lam*du[j].y);
    }
}

// ---------------- launch ---------------------------------------------------
extern "C" void kernel_launch(void* const* d_in, const int* in_sizes, int n_in,
                              void* d_out, int out_size){
    const float* u     = (const float*)d_in[0];   // (4,320,320,2)
    const float* f     = (const float*)d_in[1];   // (4,15,320,320,2)
    const float* coil  = (const float*)d_in[2];   // (4,15,320,320,2)
    const float* mask  = (const float*)d_in[3];   // (4,320,320)
    const float* ck    = (const float*)d_in[4];   // (32,1,11,11,2)
    const float* w_    = (const float*)d_in[5];   // (1,32,1,1,31)
    const float* mu_   = (const float*)d_in[6];   // (31,)
    const float* sig   = (const float*)d_in[7];   // (1,)
    const float* lamb  = (const float*)d_in[8];   // (1,)
    float* outp = (float*)d_out;

    kpad<<<(NB*UPD*UPD + 255)/256, 256>>>(u);
    kconv_rbf<<<dim3(11, 11, NB*FEATS), dim3(32, 8)>>>(ck, w_, mu_, sig);
    kconvT<<<dim3(10, 10, NB), dim3(32, 8)>>>(ck);
    kfft_row_fwd<<<NB*NC*80, 320>>>(u, coil);
    kfft_col<<<NB*NC*80, 320>>>(f, mask);
    kfft_row_inv<<<NB*80, 320>>>(u, coil, lamb, outp);
}

// round 9
// speedup vs baseline: 1.1072x; 1.1072x over previous
#include <cuda_runtime.h>
#include <cuda_bf16.h>

#define NB 4
#define NC 15
#define HH 320
#define FEATS 32
#define KS 11
#define KRBF 31
#define PH 342      // reflect-padded size (320 + 2*11)
#define UPD 352     // reflect + zero conv pad (342 + 2*5)
#define FUP 344     // pitch for f_u_k rows

// ---------------- static device scratch (no allocations allowed) ----------
__device__ float2 g_up[NB*UPD*UPD];          // (ur,ui) padded input
__device__ float  g_fu[NB*FEATS*PH*FUP];     // RBF(conv(u))
__device__ float2 g_ru[NB*HH*HH];            // regularizer output (cropped, /32)
__device__ float2 g_ks[NB*NC*HH*HH];         // k-space scratch

// ---------------- complex helpers ----------------
__device__ __forceinline__ float2 cmul(float2 a, float2 b){
    return make_float2(fmaf(a.x, b.x, -a.y*b.y), fmaf(a.x, b.y, a.y*b.x));
}
__device__ __forceinline__ float2 cadd(float2 a, float2 b){
    return make_float2(a.x+b.x, a.y+b.y);
}
__device__ __forceinline__ float2 cexp_(float ang){
    float s, c; __sincosf(ang, &s, &c); return make_float2(c, s);
}

#define TWO_PI 6.28318530717958647692f

// ---------------- tf32 helpers --------------------------------------------
__device__ __forceinline__ float to_tf32(float x){
    float r; asm("cvt.rna.tf32.f32 %0, %1;" : "=f"(r) : "f"(x)); return r;
}
__device__ __forceinline__ void mma_tf32(float* d, const unsigned* a, const unsigned* b){
    asm volatile("mma.sync.aligned.m16n8k8.row.col.f32.tf32.tf32.f32 "
        "{%0,%1,%2,%3}, {%4,%5,%6,%7}, {%8,%9}, {%0,%1,%2,%3};"
        : "+f"(d[0]), "+f"(d[1]), "+f"(d[2]), "+f"(d[3])
        : "r"(a[0]), "r"(a[1]), "r"(a[2]), "r"(a[3]), "r"(b[0]), "r"(b[1]));
}

// ---------------- 320-point Stockham FFT (radix 5*4*4*4) ------------------
__device__ __forceinline__ void r4stage(const float2* __restrict__ src,
                                        float2* __restrict__ dst,
                                        int lt, int S, int M, int NN, float ds){
    int q = lt % S;
    int p = lt / S;            // p < M
    float2 a0 = src[q + S*p];
    float2 a1 = src[q + S*(p +   M)];
    float2 a2 = src[q + S*(p + 2*M)];
    float2 a3 = src[q + S*(p + 3*M)];
    float2 t0 = make_float2(a0.x+a2.x, a0.y+a2.y);
    float2 t1 = make_float2(a0.x-a2.x, a0.y-a2.y);
    float2 t2 = make_float2(a1.x+a3.x, a1.y+a3.y);
    float2 t3 = make_float2(a1.x-a3.x, a1.y-a3.y);
    float2 it3 = make_float2(-ds*t3.y, ds*t3.x);   // ds*i*t3
    float2 c0 = make_float2(t0.x+t2.x, t0.y+t2.y);
    float2 c2 = make_float2(t0.x-t2.x, t0.y-t2.y);
    float2 c1 = make_float2(t1.x+it3.x, t1.y+it3.y);
    float2 c3 = make_float2(t1.x-it3.x, t1.y-it3.y);
    float base = ds * TWO_PI * (float)p / (float)NN;
    dst[q + S*(4*p + 0)] = c0;
    dst[q + S*(4*p + 1)] = cmul(c1, cexp_(base));
    dst[q + S*(4*p + 2)] = cmul(c2, cexp_(base*2.f));
    dst[q + S*(4*p + 3)] = cmul(c3, cexp_(base*3.f));
}

__device__ void fft320(float2* __restrict__ A, float2* __restrict__ B,
                       int lt, float ds){
    if (lt < 64){
        int p = lt;
        float2 a0 = A[p], a1 = A[p+64], a2 = A[p+128], a3 = A[p+192], a4 = A[p+256];
        B[5*p] = cadd(cadd(cadd(a0,a1), cadd(a2,a3)), a4);
        #pragma unroll
        for (int k = 1; k < 5; k++){
            float2 w1 = cexp_(ds * TWO_PI * 0.2f * (float)k);
            float2 wj = w1;
            float2 c = a0;
            c = cadd(c, cmul(a1, wj)); wj = cmul(wj, w1);
            c = cadd(c, cmul(a2, wj)); wj = cmul(wj, w1);
            c = cadd(c, cmul(a3, wj)); wj = cmul(wj, w1);
            c = cadd(c, cmul(a4, wj));
            float2 tw = cexp_(ds * TWO_PI * (float)(p*k) / 320.0f);
            B[5*p + k] = cmul(c, tw);
        }
    }
    __syncthreads();
    r4stage(B, A, lt,  5, 16, 64, ds);
    __syncthreads();
    r4stage(A, B, lt, 20,  4, 16, ds);
    __syncthreads();
    r4stage(B, A, lt, 80,  1,  4, ds);
    __syncthreads();
}

// ---------------- K1: reflect + zero padding -------------------------------
__global__ void kpad(const float* __restrict__ u){
    int idx = blockIdx.x * blockDim.x + threadIdx.x;
    if (idx >= NB*UPD*UPD) return;
    int n  = idx / (UPD*UPD);
    int r  = idx % (UPD*UPD);
    int py = r / UPD, px = r % UPD;
    float2 v = make_float2(0.f, 0.f);
    if (!(py < 5 || py >= 347 || px < 5 || px >= 347)){
        int iy = py - 16, ix = px - 16;
        if (iy < 0) iy = -iy; else if (iy >= HH) iy = 2*HH - 2 - iy;
        if (ix < 0) ix = -ix; else if (ix >= HH) ix = 2*HH - 2 - ix;
        v = ((const float2*)u)[(n*HH + iy)*HH + ix];
    }
    g_up[idx] = v;
}

// ---------------- K2: fwd conv (2->32 ch) via tf32 MMA + fused RBF ---------
// block = 256 thr (8 warps); spatial tile 32 wide x 16 tall = 512 pixels.
// Warp w: 64 pixels (4 m16 tiles) x 32 oc (4 n8 tiles), K = 242 padded to 248.
__global__ __launch_bounds__(256, 2) void kconv_mma(const float* __restrict__ ck,
                                                    const float* __restrict__ w_,
                                                    const float* __restrict__ mu_,
                                                    const float* __restrict__ sigma_){
    __shared__ float s_in[26*42*2];       // tf32-rounded input tile (float2 interleaved)
    __shared__ float s_B[248*34];         // tf32 weights [k][oc], pitch 34
    __shared__ int   s_off[248];          // im2col offsets (floats) per k
    __shared__ float s_w[FEATS*KRBF];
    __shared__ float s_mu[KRBF];

    int nb = blockIdx.z;
    int x0 = blockIdx.x * 32, y0 = blockIdx.y * 16;
    int tid = threadIdx.x;

    // fills
    for (int i = tid; i < 248; i += 256){
        int tap = i >> 1, comp = i & 1;
        int ky = tap / 11, kx = tap - ky*11;
        s_off[i] = (i < 242) ? ((ky*42 + kx)*2 + comp) : 0;
    }
    for (int i = tid; i < 248*32; i += 256){
        int k = i >> 5, oc = i & 31;
        s_B[k*34 + oc] = (k < 242) ? to_tf32(ck[oc*242 + k]) : 0.f;
    }
    for (int i = tid; i < FEATS*KRBF; i += 256) s_w[i] = w_[i];
    if (tid < KRBF) s_mu[tid] = mu_[tid];
    const float2* up = g_up + nb*UPD*UPD;
    for (int i = tid; i < 26*42; i += 256){
        int r = i / 42, c = i - r*42;
        int y = y0 + r, x = x0 + c;
        float2 v = (y < UPD && x < UPD) ? up[y*UPD + x] : make_float2(0.f, 0.f);
        s_in[2*i]   = to_tf32(v.x);
        s_in[2*i+1] = to_tf32(v.y);
    }
    __syncthreads();

    int lane = tid & 31, warp = tid >> 5;
    int grp  = lane >> 2, four = lane & 3;

    int pb[4][2];
    #pragma unroll
    for (int m = 0; m < 4; m++){
        int p0 = warp*64 + m*16 + grp;
        pb[m][0] = ((p0 >> 5)*42 + (p0 & 31))*2;
        int p1 = p0 + 8;
        pb[m][1] = ((p1 >> 5)*42 + (p1 & 31))*2;
    }

    float acc[4][4][4];
    #pragma unroll
    for (int m = 0; m < 4; m++)
        #pragma unroll
        for (int n = 0; n < 4; n++)
            #pragma unroll
            for (int r = 0; r < 4; r++) acc[m][n][r] = 0.f;

    #pragma unroll 1
    for (int kc = 0; kc < 31; kc++){
        int kk = kc*8 + four;
        int o0 = s_off[kk], o1 = s_off[kk + 4];
        unsigned a[4][4];
        #pragma unroll
        for (int m = 0; m < 4; m++){
            a[m][0] = __float_as_uint(s_in[pb[m][0] + o0]);
            a[m][1] = __float_as_uint(s_in[pb[m][1] + o0]);
            a[m][2] = __float_as_uint(s_in[pb[m][0] + o1]);
            a[m][3] = __float_as_uint(s_in[pb[m][1] + o1]);
        }
        unsigned b[4][2];
        #pragma unroll
        for (int n = 0; n < 4; n++){
            b[n][0] = __float_as_uint(s_B[kk*34       + n*8 + grp]);
            b[n][1] = __float_as_uint(s_B[(kk+4)*34   + n*8 + grp]);
        }
        #pragma unroll
        for (int m = 0; m < 4; m++)
            #pragma unroll
            for (int n = 0; n < 4; n++)
                mma_tf32(acc[m][n], a[m], b[n]);
    }

    // epilogue: RBF + store
    float sg   = sigma_[0];
    float h    = 0.5f / (sg * sg);
    float mu0  = s_mu[0];
    float idel = 1.f / (s_mu[1] - s_mu[0]);

    #pragma unroll
    for (int m = 0; m < 4; m++){
        #pragma unroll
        for (int n = 0; n < 4; n++){
            #pragma unroll
            for (int r2 = 0; r2 < 4; r2++){
                int row = grp + ((r2 >> 1) << 3);
                int col = (four << 1) + (r2 & 1);
                int p  = warp*64 + m*16 + row;
                int gy = y0 + (p >> 5), gx = x0 + (p & 31);
                if (gy < PH && gx < PH){
                    int oc = n*8 + col;
                    float v = acc[m][n][r2];
                    int j = __float2int_rn((v - mu0) * idel);
                    j = max(0, min(KRBF-1, j));
                    float s_ = 0.f;
                    #pragma unroll
                    for (int d = -4; d <= 4; d++){
                        int k = j + d;
                        if ((unsigned)k < (unsigned)KRBF){
                            float dd = v - s_mu[k];
                            s_ += s_w[oc*KRBF + k] * __expf(-h * dd * dd);
                        }
                    }
                    g_fu[((nb*FEATS + oc)*PH + gy)*FUP + gx] = s_;
                }
            }
        }
    }
}

// ---------------- K3: transposed conv (32->2 ch) + crop + /32 --------------
__global__ __launch_bounds__(256) void kconvT(const float* __restrict__ ck){
    __shared__ float  sfu[42][44];
    __shared__ float2 swt[KS][KS];

    int n  = blockIdx.z;
    int x0 = blockIdx.x * 32, y0 = blockIdx.y * 32;
    int tx = threadIdx.x, ty = threadIdx.y;
    int tid = ty*32 + tx;
    int ry = ty * 4;

    float ar[4] = {0,0,0,0}, ai[4] = {0,0,0,0};

    for (int oc = 0; oc < FEATS; oc++){
        __syncthreads();
        if (tid < 121){
            int a = tid / 11, b = tid % 11;
            const float* ckp = ck + oc*242 + ((10-a)*11 + (10-b))*2;  // flipped
            swt[a][b] = make_float2(ckp[0], ckp[1]);
        }
        const float* fup = g_fu + (n*FEATS + oc)*PH*FUP;
        for (int i = tid; i < 42*42; i += 256){
            int r = i / 42, c = i % 42;
            sfu[r][c] = fup[(y0 + 6 + r)*FUP + (x0 + 6 + c)];
        }
        __syncthreads();

        #pragma unroll
        for (int kx = 0; kx < 11; kx++){
            float col[14];
            #pragma unroll
            for (int r = 0; r < 14; r++) col[r] = sfu[ry + r][tx + kx];
            #pragma unroll
            for (int ky = 0; ky < 11; ky++){
                float2 wv = swt[ky][kx];
                #pragma unroll
                for (int u = 0; u < 4; u++){
                    ar[u] = fmaf(wv.x, col[ky+u], ar[u]);
                    ai[u] = fmaf(wv.y, col[ky+u], ai[u]);
                }
            }
        }
    }

    const float inv = 1.f / (float)FEATS;
    #pragma unroll
    for (int u = 0; u < 4; u++){
        int gy = y0 + ry + u, gx = x0 + tx;
        g_ru[(n*HH + gy)*HH + gx] = make_float2(ar[u]*inv, ai[u]*inv);
    }
}

// ---------------- D1: row forward FFT of s*(u*coil) ------------------------
__global__ __launch_bounds__(320) void kfft_row_fwd(const float* __restrict__ u,
                                                    const float* __restrict__ coil){
    __shared__ float2 SA[4][320], SB[4][320];
    int b    = blockIdx.x;
    int ygrp = b % 80;
    int nc   = b / 80;
    int c    = nc % NC, n = nc / NC;
    int t    = threadIdx.x;
    int line = t / 80, lt = t % 80;
    int y    = ygrp*4 + line;

    const float2* up = (const float2*)u    + (n*HH + y)*HH;
    const float2* cp = (const float2*)coil + ((n*NC + c)*HH + y)*HH;
    #pragma unroll
    for (int j = 0; j < 4; j++){
        int x = lt + 80*j;
        float2 v = cmul(up[x], cp[x]);
        float sg = ((x + y) & 1) ? -1.f : 1.f;
        SA[line][x] = make_float2(v.x*sg, v.y*sg);
    }
    __syncthreads();
    fft320(SA[line], SB[line], lt, -1.f);

    float2* dst = g_ks + ((n*NC + c)*HH + y)*HH;
    #pragma unroll
    for (int j = 0; j < 4; j++){ int x = lt + 80*j; dst[x] = SA[line][x]; }
}

// ---------------- D2: column fwd FFT + mask/subtract + column inv FFT ------
// lane remap (line = t&3) so warps touch 4 adjacent columns -> full sectors.
__global__ __launch_bounds__(320) void kfft_col(const float* __restrict__ f,
                                                const float* __restrict__ mask){
    __shared__ float2 SA[4][320], SB[4][320];
    int b    = blockIdx.x;
    int xgrp = b % 80;
    int nc   = b / 80;
    int c    = nc % NC, n = nc / NC;
    int t    = threadIdx.x;
    int line = t & 3, lt = t >> 2;
    int x    = xgrp*4 + line;

    float2* col = g_ks + (n*NC + c)*HH*HH + x;
    #pragma unroll
    for (int j = 0; j < 4; j++){ int y = lt + 80*j; SA[line][y] = col[y*HH]; }
    __syncthreads();
    fft320(SA[line], SB[line], lt, -1.f);

    const float sc = 1.f / 320.f;   // ortho fwd; another 1/320 folded for inverse
    #pragma unroll
    for (int j = 0; j < 4; j++){
        int ky = lt + 80*j;
        float2 V = SA[line][ky];
        float  m = mask[(n*HH + ky)*HH + x];
        float2 fv = ((const float2*)f)[((n*NC + c)*HH + ky)*HH + x];
        float sg = ((ky + x) & 1) ? -1.f : 1.f;
        float wx = m * (V.x*sc - sg*fv.x);
        float wy = m * (V.y*sc - sg*fv.y);
        SA[line][ky] = make_float2(wx*sc, wy*sc);
    }
    __syncthreads();
    fft320(SA[line], SB[line], lt, 1.f);
    #pragma unroll
    for (int j = 0; j < 4; j++){ int y = lt + 80*j; col[y*HH] = SA[line][y]; }
}

// ---------------- D3: row inverse FFT + coil-combine + final output --------
__global__ __launch_bounds__(320) void kfft_row_inv(const float* __restrict__ u,
                                                    const float* __restrict__ coil,
                                                    const float* __restrict__ lamb,
                                                    float* __restrict__ outp){
    __shared__ float2 SA[4][320], SB[4][320];
    int b    = blockIdx.x;
    int ygrp = b % 80;
    int n    = b / 80;
    int t    = threadIdx.x;
    int line = t / 80, lt = t % 80;
    int y    = ygrp*4 + line;

    float2 du[4];
    #pragma unroll
    for (int j = 0; j < 4; j++) du[j] = make_float2(0.f, 0.f);

    for (int c = 0; c < NC; c++){
        const float2* src = g_ks + ((n*NC + c)*HH + y)*HH;
        __syncthreads();
        #pragma unroll
        for (int j = 0; j < 4; j++){ int x = lt + 80*j; SA[line][x] = src[x]; }
        __syncthreads();
        fft320(SA[line], SB[line], lt, 1.f);

        const float2* cp = (const float2*)coil + ((n*NC + c)*HH + y)*HH;
        #pragma unroll
        for (int j = 0; j < 4; j++){
            int x = lt + 80*j;
            float2 w2 = SA[line][x];
            float2 cc = cp[x];
            float sg = ((x + y) & 1) ? -1.f : 1.f;
            du[j].x += sg * ( w2.x*cc.x + w2.y*cc.y);
            du[j].y += sg * ( w2.y*cc.x - w2.x*cc.y);
        }
    }

    float lam = lamb[0];
    const float2* up  = (const float2*)u + (n*HH + y)*HH;
    const float2* rup = g_ru + (n*HH + y)*HH;
    float2* op = (float2*)outp + (n*HH + y)*HH;
    #pragma unroll
    for (int j = 0; j < 4; j++){
        int x = lt + 80*j;
        float2 uv = up[x];
        float2 rv = rup[x];
        op[x] = make_float2(uv.x - rv.x - lam*du[j].x,
                            uv.y - rv.y - lam*du[j].y);
    }
}

// ---------------- launch ---------------------------------------------------
extern "C" void kernel_launch(void* const* d_in, const int* in_sizes, int n_in,
                              void* d_out, int out_size){
    const float* u     = (const float*)d_in[0];   // (4,320,320,2)
    const float* f     = (const float*)d_in[1];   // (4,15,320,320,2)
    const float* coil  = (const float*)d_in[2];   // (4,15,320,320,2)
    const float* mask  = (const float*)d_in[3];   // (4,320,320)
    const float* ck    = (const float*)d_in[4];   // (32,1,11,11,2)
    const float* w_    = (const float*)d_in[5];   // (1,32,1,1,31)
    const float* mu_   = (const float*)d_in[6];   // (31,)
    const float* sig   = (const float*)d_in[7];   // (1,)
    const float* lamb  = (const float*)d_in[8];   // (1,)
    float* outp = (float*)d_out;

    kpad<<<(NB*UPD*UPD + 255)/256, 256>>>(u);
    kconv_mma<<<dim3(11, 22, NB), 256>>>(ck, w_, mu_, sig);
    kconvT<<<dim3(10, 10, NB), dim3(32, 8)>>>(ck);
    kfft_row_fwd<<<NB*NC*80, 320>>>(u, coil);
    kfft_col<<<NB*NC*80, 320>>>(f, mask);
    kfft_row_inv<<<NB*80, 320>>>(u, coil, lamb, outp);
}

// round 10
// speedup vs baseline: 1.3386x; 1.2090x over previous
#include <cuda_runtime.h>
#include <cuda_bf16.h>

#define NB 4
#define NC 15
#define HH 320
#define FEATS 32
#define KS 11
#define KRBF 31
#define PH 342      // reflect-padded size (320 + 2*11)
#define UPD 352     // reflect + zero conv pad (342 + 2*5)
#define FUP 344     // pitch for f_u_k rows

// ---------------- static device scratch (no allocations allowed) ----------
__device__ float2 g_up[NB*UPD*UPD];          // (ur,ui) padded input
__device__ float  g_fu[NB*FEATS*PH*FUP];     // RBF(conv(u))
__device__ float2 g_ru[NB*HH*HH];            // regularizer output (cropped, /32)
__device__ float2 g_ks[NB*NC*HH*HH];         // k-space scratch

// ---------------- complex helpers ----------------
__device__ __forceinline__ float2 cmul(float2 a, float2 b){
    return make_float2(fmaf(a.x, b.x, -a.y*b.y), fmaf(a.x, b.y, a.y*b.x));
}
__device__ __forceinline__ float2 cadd(float2 a, float2 b){
    return make_float2(a.x+b.x, a.y+b.y);
}
__device__ __forceinline__ float2 cexp_(float ang){
    float s, c; __sincosf(ang, &s, &c); return make_float2(c, s);
}

#define TWO_PI 6.28318530717958647692f

// ---------------- tf32 helpers --------------------------------------------
__device__ __forceinline__ float to_tf32(float x){
    float r; asm("cvt.rna.tf32.f32 %0, %1;" : "=f"(r) : "f"(x)); return r;
}
__device__ __forceinline__ void mma_tf32(float* d, const unsigned* a, const unsigned* b){
    asm volatile("mma.sync.aligned.m16n8k8.row.col.f32.tf32.tf32.f32 "
        "{%0,%1,%2,%3}, {%4,%5,%6,%7}, {%8,%9}, {%0,%1,%2,%3};"
        : "+f"(d[0]), "+f"(d[1]), "+f"(d[2]), "+f"(d[3])
        : "r"(a[0]), "r"(a[1]), "r"(a[2]), "r"(a[3]), "r"(b[0]), "r"(b[1]));
}

// ---------------- 320-point Stockham FFT (radix 5*4*4*4) ------------------
__device__ __forceinline__ void r4stage(const float2* __restrict__ src,
                                        float2* __restrict__ dst,
                                        int lt, int S, int M, int NN, float ds){
    int q = lt % S;
    int p = lt / S;            // p < M
    float2 a0 = src[q + S*p];
    float2 a1 = src[q + S*(p +   M)];
    float2 a2 = src[q + S*(p + 2*M)];
    float2 a3 = src[q + S*(p + 3*M)];
    float2 t0 = make_float2(a0.x+a2.x, a0.y+a2.y);
    float2 t1 = make_float2(a0.x-a2.x, a0.y-a2.y);
    float2 t2 = make_float2(a1.x+a3.x, a1.y+a3.y);
    float2 t3 = make_float2(a1.x-a3.x, a1.y-a3.y);
    float2 it3 = make_float2(-ds*t3.y, ds*t3.x);   // ds*i*t3
    float2 c0 = make_float2(t0.x+t2.x, t0.y+t2.y);
    float2 c2 = make_float2(t0.x-t2.x, t0.y-t2.y);
    float2 c1 = make_float2(t1.x+it3.x, t1.y+it3.y);
    float2 c3 = make_float2(t1.x-it3.x, t1.y-it3.y);
    float base = ds * TWO_PI * (float)p / (float)NN;
    dst[q + S*(4*p + 0)] = c0;
    dst[q + S*(4*p + 1)] = cmul(c1, cexp_(base));
    dst[q + S*(4*p + 2)] = cmul(c2, cexp_(base*2.f));
    dst[q + S*(4*p + 3)] = cmul(c3, cexp_(base*3.f));
}

__device__ void fft320(float2* __restrict__ A, float2* __restrict__ B,
                       int lt, float ds){
    if (lt < 64){
        int p = lt;
        float2 a0 = A[p], a1 = A[p+64], a2 = A[p+128], a3 = A[p+192], a4 = A[p+256];
        B[5*p] = cadd(cadd(cadd(a0,a1), cadd(a2,a3)), a4);
        #pragma unroll
        for (int k = 1; k < 5; k++){
            float2 w1 = cexp_(ds * TWO_PI * 0.2f * (float)k);
            float2 wj = w1;
            float2 c = a0;
            c = cadd(c, cmul(a1, wj)); wj = cmul(wj, w1);
            c = cadd(c, cmul(a2, wj)); wj = cmul(wj, w1);
            c = cadd(c, cmul(a3, wj)); wj = cmul(wj, w1);
            c = cadd(c, cmul(a4, wj));
            float2 tw = cexp_(ds * TWO_PI * (float)(p*k) / 320.0f);
            B[5*p + k] = cmul(c, tw);
        }
    }
    __syncthreads();
    r4stage(B, A, lt,  5, 16, 64, ds);
    __syncthreads();
    r4stage(A, B, lt, 20,  4, 16, ds);
    __syncthreads();
    r4stage(B, A, lt, 80,  1,  4, ds);
    __syncthreads();
}

// ---------------- K1: reflect + zero padding -------------------------------
__global__ void kpad(const float* __restrict__ u){
    int idx = blockIdx.x * blockDim.x + threadIdx.x;
    if (idx >= NB*UPD*UPD) return;
    int n  = idx / (UPD*UPD);
    int r  = idx % (UPD*UPD);
    int py = r / UPD, px = r % UPD;
    float2 v = make_float2(0.f, 0.f);
    if (!(py < 5 || py >= 347 || px < 5 || px >= 347)){
        int iy = py - 16, ix = px - 16;
        if (iy < 0) iy = -iy; else if (iy >= HH) iy = 2*HH - 2 - iy;
        if (ix < 0) ix = -ix; else if (ix >= HH) ix = 2*HH - 2 - ix;
        v = ((const float2*)u)[(n*HH + iy)*HH + ix];
    }
    g_up[idx] = v;
}

// ---------------- K2: fwd conv (2->32 ch) via tf32 MMA + fast RBF ----------
// block = 256 thr (8 warps); spatial tile 32 wide x 16 tall = 512 pixels.
// Warp w: 64 pixels (4 m16 tiles) x 32 oc (4 n8 tiles), K = 242 padded to 248.
__global__ __launch_bounds__(256, 2) void kconv_mma(const float* __restrict__ ck,
                                                    const float* __restrict__ w_,
                                                    const float* __restrict__ mu_,
                                                    const float* __restrict__ sigma_){
    __shared__ float s_in[26*42*2];       // tf32-rounded input tile (float2 interleaved)
    __shared__ float s_B[248*34];         // tf32 weights [k][oc], pitch 34
    __shared__ int   s_off[248];          // im2col offsets (floats) per k
    __shared__ float s_wx[FEATS*40];      // RBF weights, zero-padded by 4 each side
    __shared__ float s_mu[KRBF];

    int nb = blockIdx.z;
    int x0 = blockIdx.x * 32, y0 = blockIdx.y * 16;
    int tid = threadIdx.x;

    // fills
    for (int i = tid; i < 248; i += 256){
        int tap = i >> 1, comp = i & 1;
        int ky = tap / 11, kx = tap - ky*11;
        s_off[i] = (i < 242) ? ((ky*42 + kx)*2 + comp) : 0;
    }
    for (int i = tid; i < 248*32; i += 256){
        int k = i >> 5, oc = i & 31;
        s_B[k*34 + oc] = (k < 242) ? to_tf32(ck[oc*242 + k]) : 0.f;
    }
    for (int i = tid; i < FEATS*40; i += 256){
        int oc = i / 40, kk = i - oc*40;
        s_wx[i] = (kk >= 4 && kk < 4 + KRBF) ? w_[oc*KRBF + kk - 4] : 0.f;
    }
    if (tid < KRBF) s_mu[tid] = mu_[tid];
    const float2* up = g_up + nb*UPD*UPD;
    for (int i = tid; i < 26*42; i += 256){
        int r = i / 42, c = i - r*42;
        int y = y0 + r, x = x0 + c;
        float2 v = (y < UPD && x < UPD) ? up[y*UPD + x] : make_float2(0.f, 0.f);
        s_in[2*i]   = to_tf32(v.x);
        s_in[2*i+1] = to_tf32(v.y);
    }
    __syncthreads();

    int lane = tid & 31, warp = tid >> 5;
    int grp  = lane >> 2, four = lane & 3;

    int pb[4][2];
    #pragma unroll
    for (int m = 0; m < 4; m++){
        int p0 = warp*64 + m*16 + grp;
        pb[m][0] = ((p0 >> 5)*42 + (p0 & 31))*2;
        int p1 = p0 + 8;
        pb[m][1] = ((p1 >> 5)*42 + (p1 & 31))*2;
    }

    float acc[4][4][4];
    #pragma unroll
    for (int m = 0; m < 4; m++)
        #pragma unroll
        for (int n = 0; n < 4; n++)
            #pragma unroll
            for (int r = 0; r < 4; r++) acc[m][n][r] = 0.f;

    #pragma unroll 1
    for (int kc = 0; kc < 31; kc++){
        int kk = kc*8 + four;
        int o0 = s_off[kk], o1 = s_off[kk + 4];
        unsigned a[4][4];
        #pragma unroll
        for (int m = 0; m < 4; m++){
            a[m][0] = __float_as_uint(s_in[pb[m][0] + o0]);
            a[m][1] = __float_as_uint(s_in[pb[m][1] + o0]);
            a[m][2] = __float_as_uint(s_in[pb[m][0] + o1]);
            a[m][3] = __float_as_uint(s_in[pb[m][1] + o1]);
        }
        unsigned b[4][2];
        #pragma unroll
        for (int n = 0; n < 4; n++){
            b[n][0] = __float_as_uint(s_B[kk*34       + n*8 + grp]);
            b[n][1] = __float_as_uint(s_B[(kk+4)*34   + n*8 + grp]);
        }
        #pragma unroll
        for (int m = 0; m < 4; m++)
            #pragma unroll
            for (int n = 0; n < 4; n++)
                mma_tf32(acc[m][n], a[m], b[n]);
    }

    // ---- epilogue: factored RBF + store ----
    // exp(-h(t-dD)^2) = E0 * C_d * g^d,  E0=exp(-h t^2), g=exp(2hD t), C_d=exp(-h D^2 d^2)
    float sg    = sigma_[0];
    float h     = 0.5f / (sg * sg);
    float mu0   = s_mu[0];
    float delta = s_mu[1] - s_mu[0];
    float idel  = 1.f / delta;
    float c2    = 2.f * h * delta;
    float C1    = __expf(-h * delta * delta);
    float C1_2  = C1*C1;
    float C4    = C1_2*C1_2;
    float C8    = C4*C4;
    float C16   = C8*C8;
    float C9    = C8*C1;
    float tmax  = 10.f / (h * delta);     // keeps g^4 finite; both paths underflow to 0 beyond

    #pragma unroll
    for (int m = 0; m < 4; m++){
        #pragma unroll
        for (int n = 0; n < 4; n++){
            #pragma unroll
            for (int r2 = 0; r2 < 4; r2++){
                int row = grp + ((r2 >> 1) << 3);
                int col = (four << 1) + (r2 & 1);
                int p  = warp*64 + m*16 + row;
                int gy = y0 + (p >> 5), gx = x0 + (p & 31);
                if (gy < PH && gx < PH){
                    int oc = n*8 + col;
                    float v = acc[m][n][r2];
                    int j = __float2int_rn((v - mu0) * idel);
                    j = max(0, min(KRBF-1, j));
                    float t = v - fmaf((float)j, delta, mu0);
                    t = fminf(fmaxf(t, -tmax), tmax);
                    float E0 = __expf(-h*t*t);
                    float gpl = __expf(c2*t);
                    float gmi = __expf(-c2*t);
                    float g2 = gpl*gpl, g3 = g2*gpl, g4 = g2*g2;
                    float q2 = gmi*gmi, q3 = q2*gmi, q4 = q2*q2;
                    const float* wp = s_wx + oc*40 + j;
                    float s_ = wp[4]
                        + C1 *(wp[5]*gpl + wp[3]*gmi)
                        + C4 *(wp[6]*g2  + wp[2]*q2)
                        + C9 *(wp[7]*g3  + wp[1]*q3)
                        + C16*(wp[8]*g4  + wp[0]*q4);
                    g_fu[((nb*FEATS + oc)*PH + gy)*FUP + gx] = E0 * s_;
                }
            }
        }
    }
}

// ---------------- K3: transposed conv via tf32 MMA (shifted-PS trick) ------
// out[Y,X] = sum_j PS_j[Y,X+j];  PS_j: GEMM K=(oc,ky,q)=32*11*3, N=8=(comp,j)
// block: 256 thr, PS tile 32 wide x 16 tall; output cols stride 29 per block.
#define CTW 29
__global__ __launch_bounds__(256) void kconvT_mma(const float* __restrict__ ck){
    __shared__ float s_B[FEATS*33*8];   // [oc][k][n] tf32 weights (33 k-rows/oc)
    __shared__ float s_G[26*40];        // per-oc fu tile (tf32)
    __shared__ int   s_off[40];

    int nb = blockIdx.z;
    int x0 = blockIdx.x * CTW, y0 = blockIdx.y * 16;
    int tid = threadIdx.x;
    int lane = tid & 31, warp = tid >> 5;
    int grp  = lane >> 2, four = lane & 3;

    // B fill: k=(ky*3+q), n=(comp*4+j), W = flipped ck;  kx = 4q+j (<=10)
    for (int i = tid; i < FEATS*33*8; i += 256){
        int oc = i / (33*8);
        int r  = i - oc*(33*8);
        int k  = r >> 3, n = r & 7;
        int ky = k / 3, q = k - ky*3;
        int comp = n >> 2, j = n & 3;
        int kx = 4*q + j;
        float v = 0.f;
        if (kx <= 10)
            v = to_tf32(ck[(oc*121 + (10-ky)*11 + (10-kx))*2 + comp]);
        s_B[i] = v;
    }
    for (int i = tid; i < 40; i += 256)
        s_off[i] = (i < 33) ? ((i/3)*40 + (i%3)*4) : 0;

    int pb[4][2];
    #pragma unroll
    for (int m = 0; m < 4; m++){
        int p0 = warp*64 + m*16 + grp;
        pb[m][0] = (p0 >> 5)*40 + (p0 & 31);
        int p1 = p0 + 8;
        pb[m][1] = (p1 >> 5)*40 + (p1 & 31);
    }

    float acc[4][4];
    #pragma unroll
    for (int m = 0; m < 4; m++)
        #pragma unroll
        for (int r = 0; r < 4; r++) acc[m][r] = 0.f;

    #pragma unroll 1
    for (int oc = 0; oc < FEATS; oc++){
        __syncthreads();
        const float* fup = g_fu + (nb*FEATS + oc)*PH*FUP;
        for (int i = tid; i < 26*40; i += 256){
            int r = i / 40, c = i - r*40;
            int gr = y0 + 6 + r, gc = x0 + 6 + c;
            s_G[i] = (gc < FUP) ? to_tf32(fup[gr*FUP + gc]) : 0.f;
        }
        __syncthreads();

        const float* Boc = s_B + oc*33*8;
        #pragma unroll
        for (int ks = 0; ks < 5; ks++){
            int k0 = ks*8 + four, k1 = k0 + 4;
            int o0 = s_off[k0], o1 = s_off[k1];
            unsigned b[2];
            b[0] = (k0 < 33) ? __float_as_uint(Boc[k0*8 + grp]) : 0u;
            b[1] = (k1 < 33) ? __float_as_uint(Boc[k1*8 + grp]) : 0u;
            #pragma unroll
            for (int m = 0; m < 4; m++){
                unsigned a[4];
                a[0] = __float_as_uint(s_G[pb[m][0] + o0]);
                a[1] = __float_as_uint(s_G[pb[m][1] + o0]);
                a[2] = __float_as_uint(s_G[pb[m][0] + o1]);
                a[3] = __float_as_uint(s_G[pb[m][1] + o1]);
                mma_tf32(acc[m], a, b);
            }
        }
    }

    // combine shifted partial sums through smem (alias s_B; mma phase done)
    __syncthreads();
    float* s_PS = s_B;       // needs 512*9 = 4608 floats
    #pragma unroll
    for (int m = 0; m < 4; m++){
        #pragma unroll
        for (int r2 = 0; r2 < 4; r2++){
            int p = warp*64 + m*16 + grp + ((r2 >> 1) << 3);
            int n = (four << 1) + (r2 & 1);
            s_PS[p*9 + n] = acc[m][r2];
        }
    }
    __syncthreads();

    const float inv = 1.f / (float)FEATS;
    for (int i = tid; i < 512; i += 256){
        int row = i >> 5, col = i & 31;
        int X = x0 + col, Y = y0 + row;
        if (col < CTW && X < HH){
            float orr = 0.f, oii = 0.f;
            #pragma unroll
            for (int j = 0; j < 4; j++){
                orr += s_PS[(i + j)*9 + j];
                oii += s_PS[(i + j)*9 + 4 + j];
            }
            g_ru[(nb*HH + Y)*HH + X] = make_float2(orr*inv, oii*inv);
        }
    }
}

// ---------------- D1: row forward FFT of s*(u*coil) ------------------------
__global__ __launch_bounds__(320) void kfft_row_fwd(const float* __restrict__ u,
                                                    const float* __restrict__ coil){
    __shared__ float2 SA[4][320], SB[4][320];
    int b    = blockIdx.x;
    int ygrp = b % 80;
    int nc   = b / 80;
    int c    = nc % NC, n = nc / NC;
    int t    = threadIdx.x;
    int line = t / 80, lt = t % 80;
    int y    = ygrp*4 + line;

    const float2* up = (const float2*)u    + (n*HH + y)*HH;
    const float2* cp = (const float2*)coil + ((n*NC + c)*HH + y)*HH;
    #pragma unroll
    for (int j = 0; j < 4; j++){
        int x = lt + 80*j;
        float2 v = cmul(up[x], cp[x]);
        float sg = ((x + y) & 1) ? -1.f : 1.f;
        SA[line][x] = make_float2(v.x*sg, v.y*sg);
    }
    __syncthreads();
    fft320(SA[line], SB[line], lt, -1.f);

    float2* dst = g_ks + ((n*NC + c)*HH + y)*HH;
    #pragma unroll
    for (int j = 0; j < 4; j++){ int x = lt + 80*j; dst[x] = SA[line][x]; }
}

// ---------------- D2: column fwd FFT + mask/subtract + column inv FFT ------
__global__ __launch_bounds__(320) void kfft_col(const float* __restrict__ f,
                                                const float* __restrict__ mask){
    __shared__ float2 SA[4][320], SB[4][320];
    int b    = blockIdx.x;
    int xgrp = b % 80;
    int nc   = b / 80;
    int c    = nc % NC, n = nc / NC;
    int t    = threadIdx.x;
    int line = t & 3, lt = t >> 2;
    int x    = xgrp*4 + line;

    float2* col = g_ks + (n*NC + c)*HH*HH + x;
    #pragma unroll
    for (int j = 0; j < 4; j++){ int y = lt + 80*j; SA[line][y] = col[y*HH]; }
    __syncthreads();
    fft320(SA[line], SB[line], lt, -1.f);

    const float sc = 1.f / 320.f;
    #pragma unroll
    for (int j = 0; j < 4; j++){
        int ky = lt + 80*j;
        float2 V = SA[line][ky];
        float  m = mask[(n*HH + ky)*HH + x];
        float2 fv = ((const float2*)f)[((n*NC + c)*HH + ky)*HH + x];
        float sg = ((ky + x) & 1) ? -1.f : 1.f;
        float wx = m * (V.x*sc - sg*fv.x);
        float wy = m * (V.y*sc - sg*fv.y);
        SA[line][ky] = make_float2(wx*sc, wy*sc);
    }
    __syncthreads();
    fft320(SA[line], SB[line], lt, 1.f);
    #pragma unroll
    for (int j = 0; j < 4; j++){ int y = lt + 80*j; col[y*HH] = SA[line][y]; }
}

// ---------------- D3: row inverse FFT + coil-combine + final output --------
__global__ __launch_bounds__(320) void kfft_row_inv(const float* __restrict__ u,
                                                    const float* __restrict__ coil,
                                                    const float* __restrict__ lamb,
                                                    float* __restrict__ outp){
    __shared__ float2 SA[4][320], SB[4][320];
    int b    = blockIdx.x;
    int ygrp = b % 80;
    int n    = b / 80;
    int t    = threadIdx.x;
    int line = t / 80, lt = t % 80;
    int y    = ygrp*4 + line;

    float2 du[4];
    #pragma unroll
    for (int j = 0; j < 4; j++) du[j] = make_float2(0.f, 0.f);

    for (int c = 0; c < NC; c++){
        const float2* src = g_ks + ((n*NC + c)*HH + y)*HH;
        __syncthreads();
        #pragma unroll
        for (int j = 0; j < 4; j++){ int x = lt + 80*j; SA[line][x] = src[x]; }
        __syncthreads();
        fft320(SA[line], SB[line], lt, 1.f);

        const float2* cp = (const float2*)coil + ((n*NC + c)*HH + y)*HH;
        #pragma unroll
        for (int j = 0; j < 4; j++){
            int x = lt + 80*j;
            float2 w2 = SA[line][x];
            float2 cc = cp[x];
            float sg = ((x + y) & 1) ? -1.f : 1.f;
            du[j].x += sg * ( w2.x*cc.x + w2.y*cc.y);
            du[j].y += sg * ( w2.y*cc.x - w2.x*cc.y);
        }
    }

    float lam = lamb[0];
    const float2* up  = (const float2*)u + (n*HH + y)*HH;
    const float2* rup = g_ru + (n*HH + y)*HH;
    float2* op = (float2*)outp + (n*HH + y)*HH;
    #pragma unroll
    for (int j = 0; j < 4; j++){
        int x = lt + 80*j;
        float2 uv = up[x];
        float2 rv = rup[x];
        op[x] = make_float2(uv.x - rv.x - lam*du[j].x,
                            uv.y - rv.y - lam*du[j].y);
    }
}

// ---------------- launch ---------------------------------------------------
extern "C" void kernel_launch(void* const* d_in, const int* in_sizes, int n_in,
                              void* d_out, int out_size){
    const float* u     = (const float*)d_in[0];   // (4,320,320,2)
    const float* f     = (const float*)d_in[1];   // (4,15,320,320,2)
    const float* coil  = (const float*)d_in[2];   // (4,15,320,320,2)
    const float* mask  = (const float*)d_in[3];   // (4,320,320)
    const float* ck    = (const float*)d_in[4];   // (32,1,11,11,2)
    const float* w_    = (const float*)d_in[5];   // (1,32,1,1,31)
    const float* mu_   = (const float*)d_in[6];   // (31,)
    const float* sig   = (const float*)d_in[7];   // (1,)
    const float* lamb  = (const float*)d_in[8];   // (1,)
    float* outp = (float*)d_out;

    kpad<<<(NB*UPD*UPD + 255)/256, 256>>>(u);
    kconv_mma<<<dim3(11, 22, NB), 256>>>(ck, w_, mu_, sig);
    kconvT_mma<<<dim3(12, 20, NB), 256>>>(ck);
    kfft_row_fwd<<<NB*NC*80, 320>>>(u, coil);
    kfft_col<<<NB*NC*80, 320>>>(f, mask);
    kfft_row_inv<<<NB*80, 320>>>(u, coil, lamb, outp);
}